// round 1
// baseline (speedup 1.0000x reference)
#include <cuda_runtime.h>

// Problem constants
#define BB 8192
#define TT 256
#define FF 16
#define HH 8
#define FUT 8

__device__ __forceinline__ float sigf(float x) {
    // 1/(1+exp(-x)) via MUFU EX2 + MUFU RCP
    return __fdividef(1.0f, 1.0f + __expf(-x));
}
__device__ __forceinline__ float tanhf_fast(float x) {
    // 2*sigmoid(2x) - 1, same MUFU budget, ~1e-7 accuracy
    return __fdividef(2.0f, 1.0f + __expf(-2.0f * x)) - 1.0f;
}

__global__ __launch_bounds__(256) void LSTM_91122026152229_kernel(
    const float* __restrict__ past,   // [B,T,F]
    const float* __restrict__ fut,    // [B,FUT]
    const float* __restrict__ W1, const float* __restrict__ U1, const float* __restrict__ b1,
    const float* __restrict__ W2, const float* __restrict__ U2, const float* __restrict__ b2,
    const float* __restrict__ Wd1, const float* __restrict__ bd1,
    const float* __restrict__ Wd2, const float* __restrict__ bd2,
    const float* __restrict__ Wo, const float* __restrict__ bo,
    float* __restrict__ out)          // [B,4]
{
    // All weights in shared memory (~6.4 KB)
    __shared__ float sW1[FF * 32];   // [16][32]
    __shared__ float sU1[HH * 32];   // [8][32]
    __shared__ float sW2[HH * 32];   // [8][32]
    __shared__ float sU2[HH * 32];   // [8][32]
    __shared__ float sb1[32], sb2[32];
    __shared__ float sWd1[16 * 8];   // [16][8]
    __shared__ float sWd2[8 * 8];    // [8][8]
    __shared__ float sWo[8 * 4];     // [8][4]
    __shared__ float sbd1[8], sbd2[8], sbo[4];

    const int tid = threadIdx.x;
    for (int i = tid; i < FF * 32; i += 256) sW1[i] = W1[i];
    for (int i = tid; i < HH * 32; i += 256) sU1[i] = U1[i];
    for (int i = tid; i < HH * 32; i += 256) sW2[i] = W2[i];
    for (int i = tid; i < HH * 32; i += 256) sU2[i] = U2[i];
    if (tid < 32)  sb1[tid] = b1[tid];
    if (tid >= 32 && tid < 64) sb2[tid - 32] = b2[tid - 32];
    if (tid >= 64 && tid < 192) sWd1[tid - 64] = Wd1[tid - 64];
    if (tid >= 192 && tid < 256) sWd2[tid - 192] = Wd2[tid - 192];
    if (tid >= 128 && tid < 160) sWo[tid - 128] = Wo[tid - 128];
    if (tid >= 160 && tid < 168) sbd1[tid - 160] = bd1[tid - 160];
    if (tid >= 168 && tid < 176) sbd2[tid - 168] = bd2[tid - 168];
    if (tid >= 176 && tid < 180) sbo[tid - 176] = bo[tid - 176];
    __syncthreads();

    // Thread mapping: 8 threads per batch element; thread owns hidden unit u.
    const int g = blockIdx.x * 256 + tid;      // 0..65535
    const int e = g >> 3;                      // batch element
    const int u = g & 7;                       // hidden unit
    const int lane = tid & 31;
    const int base8 = lane & 24;               // first lane of my 8-lane group

    const float4* __restrict__ xp =
        (const float4*)(past + (size_t)e * (TT * FF));

    float h1 = 0.f, c1 = 0.f, h2 = 0.f, c2 = 0.f;
    const float bi1 = sb1[u], bf1 = sb1[u + 8], bg1 = sb1[u + 16], bq1 = sb1[u + 24];
    const float bi2 = sb2[u], bf2 = sb2[u + 8], bg2 = sb2[u + 16], bq2 = sb2[u + 24];

    for (int t = 0; t < TT; t++) {
        // x_t for my element: 16 floats (8-lane broadcast loads, L1-resident)
        const float4 xa = xp[t * 4 + 0];
        const float4 xb = xp[t * 4 + 1];
        const float4 xc = xp[t * 4 + 2];
        const float4 xd = xp[t * 4 + 3];
        const float xr[16] = { xa.x, xa.y, xa.z, xa.w,  xb.x, xb.y, xb.z, xb.w,
                               xc.x, xc.y, xc.z, xc.w,  xd.x, xd.y, xd.z, xd.w };

        // ---- layer 1 ----
        float zi = bi1, zf = bf1, zg = bg1, zo = bq1;
        #pragma unroll
        for (int k = 0; k < 16; k++) {
            const float xv = xr[k];
            zi += xv * sW1[k * 32 + u];
            zf += xv * sW1[k * 32 + u + 8];
            zg += xv * sW1[k * 32 + u + 16];
            zo += xv * sW1[k * 32 + u + 24];
        }
        #pragma unroll
        for (int k = 0; k < 8; k++) {
            const float hk = __shfl_sync(0xffffffffu, h1, base8 + k);
            zi += hk * sU1[k * 32 + u];
            zf += hk * sU1[k * 32 + u + 8];
            zg += hk * sU1[k * 32 + u + 16];
            zo += hk * sU1[k * 32 + u + 24];
        }
        c1 = sigf(zf) * c1 + sigf(zi) * tanhf_fast(zg);
        h1 = sigf(zo) * tanhf_fast(c1);

        // ---- layer 2 (input = h1 vector, recurrent = h2 vector) ----
        float yi = bi2, yf = bf2, yg = bg2, yo = bq2;
        #pragma unroll
        for (int k = 0; k < 8; k++) {
            const float h1k = __shfl_sync(0xffffffffu, h1, base8 + k);
            const float h2k = __shfl_sync(0xffffffffu, h2, base8 + k);
            yi += h1k * sW2[k * 32 + u]      + h2k * sU2[k * 32 + u];
            yf += h1k * sW2[k * 32 + u + 8]  + h2k * sU2[k * 32 + u + 8];
            yg += h1k * sW2[k * 32 + u + 16] + h2k * sU2[k * 32 + u + 16];
            yo += h1k * sW2[k * 32 + u + 24] + h2k * sU2[k * 32 + u + 24];
        }
        c2 = sigf(yf) * c2 + sigf(yi) * tanhf_fast(yg);
        h2 = sigf(yo) * tanhf_fast(c2);
    }

    // ---- MLP head: concat(h2, fut) -> 8 relu -> 8 relu -> 4 ----
    float d1 = sbd1[u];
    #pragma unroll
    for (int k = 0; k < 8; k++) {
        const float h2k = __shfl_sync(0xffffffffu, h2, base8 + k);
        d1 += h2k * sWd1[k * 8 + u];
    }
    const float* __restrict__ fp = fut + (size_t)e * FUT;
    #pragma unroll
    for (int k = 0; k < 8; k++) d1 += fp[k] * sWd1[(8 + k) * 8 + u];
    d1 = fmaxf(d1, 0.f);

    float d2 = sbd2[u];
    #pragma unroll
    for (int k = 0; k < 8; k++) {
        const float d1k = __shfl_sync(0xffffffffu, d1, base8 + k);
        d2 += d1k * sWd2[k * 8 + u];
    }
    d2 = fmaxf(d2, 0.f);

    float o = (u < 4) ? sbo[u] : 0.f;
    #pragma unroll
    for (int k = 0; k < 8; k++) {
        const float d2k = __shfl_sync(0xffffffffu, d2, base8 + k);
        if (u < 4) o += d2k * sWo[k * 4 + u];
    }
    if (u < 4) out[(size_t)e * 4 + u] = o;
}

extern "C" void kernel_launch(void* const* d_in, const int* in_sizes, int n_in,
                              void* d_out, int out_size) {
    // metadata order: img, past_metadata, future_metadata, W1,U1,b1, W2,U2,b2,
    //                 Wd1,bd1, Wd2,bd2, Wo,bo
    const float* past = (const float*)d_in[1];
    const float* fut  = (const float*)d_in[2];
    const float* W1   = (const float*)d_in[3];
    const float* U1   = (const float*)d_in[4];
    const float* b1   = (const float*)d_in[5];
    const float* W2   = (const float*)d_in[6];
    const float* U2   = (const float*)d_in[7];
    const float* b2   = (const float*)d_in[8];
    const float* Wd1  = (const float*)d_in[9];
    const float* bd1  = (const float*)d_in[10];
    const float* Wd2  = (const float*)d_in[11];
    const float* bd2  = (const float*)d_in[12];
    const float* Wo   = (const float*)d_in[13];
    const float* bo   = (const float*)d_in[14];

    // 65536 threads: 8 per batch element
    LSTM_91122026152229_kernel<<<(BB * HH) / 256, 256>>>(
        past, fut, W1, U1, b1, W2, U2, b2, Wd1, bd1, Wd2, bd2, Wo, bo,
        (float*)d_out);
}